// round 1
// baseline (speedup 1.0000x reference)
#include <cuda_runtime.h>
#include <math.h>

// ---------------- problem constants ----------------
#define NPIX   16384     // B*H*W = 16*32*32
#define BATCH  16
#define CDIM   512
#define HWSZ   1024      // 32*32
#define FCH    1024      // pin output channels
#define DWD    992       // depthwise channels
#define HDIM   2048      // fc1 output

// ---------------- scratch (device globals; no allocation) ----------------
__device__ float g_xt   [NPIX * CDIM];   // x in NHWC
__device__ float g_xln  [NPIX * CDIM];   // LN1 output
__device__ float g_fused[NPIX * FCH];    // pin output
__device__ float g_dw   [NPIX * DWD];    // depthwise output (+bias)
__device__ float g_bufA [NPIX * CDIM];   // gated chain ping
__device__ float g_bufB [NPIX * CDIM];   // gated chain pong
__device__ float g_x1   [NPIX * CDIM];   // x + g1*gnconv  (NHWC)
__device__ float g_ln2o [NPIX * CDIM];   // LN2 output
__device__ float g_h    [NPIX * HDIM];   // fc1+gelu output
__device__ float g_m    [NPIX * CDIM];   // fc2 output

// ---------------- NCHW -> NHWC transpose ----------------
__global__ void k_transpose_in(const float* __restrict__ x, float* __restrict__ xt)
{
    __shared__ float t[32][33];
    int b  = blockIdx.z;
    int c0 = blockIdx.y * 32;
    int hw0 = blockIdx.x * 32;
    int tx = threadIdx.x, ty = threadIdx.y;
#pragma unroll
    for (int i = 0; i < 4; i++) {
        int c = c0 + ty + 8 * i;
        t[ty + 8 * i][tx] = x[((size_t)(b * CDIM + c)) * HWSZ + hw0 + tx];
    }
    __syncthreads();
#pragma unroll
    for (int i = 0; i < 4; i++) {
        int p = b * HWSZ + hw0 + ty + 8 * i;
        xt[(size_t)p * CDIM + c0 + tx] = t[tx][ty + 8 * i];
    }
}

// ---------------- row LayerNorm over 512 channels (1 warp / row) ----------------
__global__ void k_ln_rows(const float* __restrict__ in, const float* __restrict__ w,
                          const float* __restrict__ b, float* __restrict__ out)
{
    int row  = blockIdx.x * 8 + (threadIdx.x >> 5);
    int lane = threadIdx.x & 31;
    const float4* r4 = (const float4*)(in + (size_t)row * CDIM);
    float4 v[4];
    float s = 0.f, ss = 0.f;
#pragma unroll
    for (int i = 0; i < 4; i++) {
        v[i] = r4[lane + 32 * i];
        s  += v[i].x + v[i].y + v[i].z + v[i].w;
        ss += v[i].x * v[i].x + v[i].y * v[i].y + v[i].z * v[i].z + v[i].w * v[i].w;
    }
#pragma unroll
    for (int o = 16; o; o >>= 1) {
        s  += __shfl_xor_sync(0xffffffffu, s, o);
        ss += __shfl_xor_sync(0xffffffffu, ss, o);
    }
    float mu  = s * (1.f / 512.f);
    float var = ss * (1.f / 512.f) - mu * mu;
    float rs  = rsqrtf(var + 1e-6f);
    float4* o4 = (float4*)(out + (size_t)row * CDIM);
    const float4* w4 = (const float4*)w;
    const float4* b4 = (const float4*)b;
#pragma unroll
    for (int i = 0; i < 4; i++) {
        int idx = lane + 32 * i;
        float4 ww = w4[idx], bb = b4[idx], vv = v[i], res;
        res.x = (vv.x - mu) * rs * ww.x + bb.x;
        res.y = (vv.y - mu) * rs * ww.y + bb.y;
        res.z = (vv.z - mu) * rs * ww.z + bb.z;
        res.w = (vv.w - mu) * rs * ww.w + bb.w;
        o4[idx] = res;
    }
}

// ---------------- generic TN GEMM: out[M,N] = A[M,K] @ W[N,K]^T + bias, fused epilogues ----
// EPI 0: +bias
// EPI 1: (+bias) * E1[m*lde1 + e1off + n]          (dw gate)
// EPI 2: E1[m*512 + n] + E2[n] * (+bias)           (pout residual: x + g1*y)
// EPI 3: exact GELU(+bias)
template <int BM, int BN, int BK, int EPI>
__global__ void __launch_bounds__((BM / 8) * (BN / 8))
k_gemm_tn(const float* __restrict__ A, const float* __restrict__ W,
          const float* __restrict__ bias, float* __restrict__ out,
          int M, int N, int K,
          const float* __restrict__ E1, int lde1, int e1off,
          const float* __restrict__ E2)
{
    constexpr int TM = 8, TN = 8;
    constexpr int NT = (BM / TM) * (BN / TN);
    __shared__ float As[BK][BM];
    __shared__ float Ws[BK][BN];

    int tid = threadIdx.x;
    int tr = tid / (BN / TN);
    int tc = tid % (BN / TN);
    int m0 = blockIdx.y * BM;
    int n0 = blockIdx.x * BN;

    float acc[TM][TN];
#pragma unroll
    for (int i = 0; i < TM; i++)
#pragma unroll
        for (int j = 0; j < TN; j++) acc[i][j] = 0.f;

    for (int k0 = 0; k0 < K; k0 += BK) {
#pragma unroll
        for (int i = tid; i < BM * BK / 4; i += NT) {
            int r = i / (BK / 4), c4 = i % (BK / 4);
            float4 v = *(const float4*)(A + (size_t)(m0 + r) * K + k0 + c4 * 4);
            As[c4 * 4 + 0][r] = v.x; As[c4 * 4 + 1][r] = v.y;
            As[c4 * 4 + 2][r] = v.z; As[c4 * 4 + 3][r] = v.w;
        }
#pragma unroll
        for (int i = tid; i < BN * BK / 4; i += NT) {
            int r = i / (BK / 4), c4 = i % (BK / 4);
            float4 v = *(const float4*)(W + (size_t)(n0 + r) * K + k0 + c4 * 4);
            Ws[c4 * 4 + 0][r] = v.x; Ws[c4 * 4 + 1][r] = v.y;
            Ws[c4 * 4 + 2][r] = v.z; Ws[c4 * 4 + 3][r] = v.w;
        }
        __syncthreads();
#pragma unroll
        for (int k = 0; k < BK; k++) {
            float ra[TM], rb[TN];
            *(float4*)(ra)     = *(const float4*)&As[k][tr * 8];
            *(float4*)(ra + 4) = *(const float4*)&As[k][tr * 8 + 4];
            *(float4*)(rb)     = *(const float4*)&Ws[k][tc * 8];
            *(float4*)(rb + 4) = *(const float4*)&Ws[k][tc * 8 + 4];
#pragma unroll
            for (int i = 0; i < TM; i++)
#pragma unroll
                for (int j = 0; j < TN; j++) acc[i][j] += ra[i] * rb[j];
        }
        __syncthreads();
    }

    int m = m0 + tr * TM;
    int n = n0 + tc * TN;
#pragma unroll
    for (int i = 0; i < TM; i++) {
        size_t ro = (size_t)(m + i) * N + n;
#pragma unroll
        for (int j = 0; j < TN; j++) {
            float v = acc[i][j] + bias[n + j];
            if (EPI == 1) v *= E1[(size_t)(m + i) * lde1 + e1off + n + j];
            if (EPI == 2) v = E1[(size_t)(m + i) * CDIM + n + j] + E2[n + j] * v;
            if (EPI == 3) v = 0.5f * v * (1.f + erff(v * 0.70710678118654752f));
            out[ro + j] = v;
        }
    }
}

// ---------------- depthwise 7x7 conv on fused[:, 32:1024] -> g_dw ----------------
// block = 256 threads = 32 channels x 8 pixels; weights staged in smem
__global__ void k_dwconv(const float* __restrict__ fused, const float* __restrict__ wgt,
                         const float* __restrict__ bias, float* __restrict__ out)
{
    __shared__ float sw[32 * 49];
    int cg = blockIdx.x;                       // 0..30 (31 groups of 32 ch)
    int cl = threadIdx.x & 31;
    int c  = cg * 32 + cl;
    for (int i = threadIdx.x; i < 32 * 49; i += 256)
        sw[i] = wgt[cg * 32 * 49 + i];
    __syncthreads();

    int p = blockIdx.y * 8 + (threadIdx.x >> 5);
    int b = p >> 10, hw = p & 1023, h = hw >> 5, w = hw & 31;
    const float* base = fused + (size_t)(b * HWSZ) * FCH + 32 + c;
    float acc = bias[c];
#pragma unroll
    for (int kh = 0; kh < 7; kh++) {
        int hh = h + kh - 3;
        if ((unsigned)hh < 32u) {
#pragma unroll
            for (int kw = 0; kw < 7; kw++) {
                int ww = w + kw - 3;
                if ((unsigned)ww < 32u)
                    acc += base[(size_t)(hh * 32 + ww) * FCH] * sw[cl * 49 + kh * 7 + kw];
            }
        }
    }
    out[(size_t)p * DWD + c] = acc;
}

// ---------------- y0 = pwa * dw0  (width 32) ----------------
__global__ void k_mul_pwa(const float* __restrict__ fused, const float* __restrict__ dw,
                          float* __restrict__ out)
{
    int idx = blockIdx.x * 256 + threadIdx.x;   // over NPIX*32
    int p = idx >> 5, c = idx & 31;
    out[idx] = fused[(size_t)p * FCH + c] * dw[(size_t)p * DWD + c];
}

// ---------------- final: out(NCHW) = x1 + g2*m, with NHWC->NCHW transpose ----------------
__global__ void k_final_out(const float* __restrict__ x1, const float* __restrict__ m,
                            const float* __restrict__ g2, float* __restrict__ out)
{
    __shared__ float t[32][33];
    int b  = blockIdx.z;
    int c0 = blockIdx.y * 32;
    int hw0 = blockIdx.x * 32;
    int tx = threadIdx.x, ty = threadIdx.y;
#pragma unroll
    for (int i = 0; i < 4; i++) {
        int p = b * HWSZ + hw0 + ty + 8 * i;
        int c = c0 + tx;
        size_t o = (size_t)p * CDIM + c;
        t[ty + 8 * i][tx] = x1[o] + g2[c] * m[o];
    }
    __syncthreads();
#pragma unroll
    for (int i = 0; i < 4; i++) {
        int c = c0 + ty + 8 * i;
        out[((size_t)(b * CDIM + c)) * HWSZ + hw0 + tx] = t[tx][ty + 8 * i];
    }
}

// ---------------- host orchestration ----------------
static float* sym(const void* s)
{
    void* p = nullptr;
    cudaGetSymbolAddress(&p, s);
    return (float*)p;
}

extern "C" void kernel_launch(void* const* d_in, const int* in_sizes, int n_in,
                              void* d_out, int out_size)
{
    const float* x      = (const float*)d_in[0];
    const float* ln1_w  = (const float*)d_in[1];
    const float* ln1_b  = (const float*)d_in[2];
    const float* pin_w  = (const float*)d_in[3];
    const float* pin_b  = (const float*)d_in[4];
    const float* dw_w   = (const float*)d_in[5];
    const float* dw_b   = (const float*)d_in[6];
    const float* pw0_w  = (const float*)d_in[7];
    const float* pw0_b  = (const float*)d_in[8];
    const float* pw1_w  = (const float*)d_in[9];
    const float* pw1_b  = (const float*)d_in[10];
    const float* pw2_w  = (const float*)d_in[11];
    const float* pw2_b  = (const float*)d_in[12];
    const float* pw3_w  = (const float*)d_in[13];
    const float* pw3_b  = (const float*)d_in[14];
    const float* pout_w = (const float*)d_in[15];
    const float* pout_b = (const float*)d_in[16];
    const float* ln2_w  = (const float*)d_in[17];
    const float* ln2_b  = (const float*)d_in[18];
    const float* fc1_w  = (const float*)d_in[19];
    const float* fc1_b  = (const float*)d_in[20];
    const float* fc2_w  = (const float*)d_in[21];
    const float* fc2_b  = (const float*)d_in[22];
    const float* g1     = (const float*)d_in[23];
    const float* g2     = (const float*)d_in[24];
    float* out = (float*)d_out;

    float* xt    = sym(g_xt);
    float* xln   = sym(g_xln);
    float* fused = sym(g_fused);
    float* dwb   = sym(g_dw);
    float* bufA  = sym(g_bufA);
    float* bufB  = sym(g_bufB);
    float* x1    = sym(g_x1);
    float* ln2o  = sym(g_ln2o);
    float* hbuf  = sym(g_h);
    float* mbuf  = sym(g_m);

    dim3 tpb32(32, 8);
    dim3 tgrid(32, 16, BATCH);

    // 1. NCHW -> NHWC
    k_transpose_in<<<tgrid, tpb32>>>(x, xt);
    // 2. LN1
    k_ln_rows<<<NPIX / 8, 256>>>(xt, ln1_w, ln1_b, xln);
    // 3. pin: [16384,512] @ [1024,512]^T -> fused [16384,1024]
    k_gemm_tn<128, 128, 32, 0><<<dim3(FCH / 128, NPIX / 128), 256>>>(
        xln, pin_w, pin_b, fused, NPIX, FCH, CDIM, nullptr, 0, 0, nullptr);
    // 4. depthwise 7x7 over 992 channels
    k_dwconv<<<dim3(31, NPIX / 8), 256>>>(fused, dw_w, dw_b, dwb);
    // 5. y0 = pwa * dw0
    k_mul_pwa<<<NPIX * 32 / 256, 256>>>(fused, dwb, bufA);
    // 6. gated pw chain (dw-gate epilogues)
    k_gemm_tn<128, 64, 32, 1><<<dim3(1, NPIX / 128), 128>>>(
        bufA, pw0_w, pw0_b, bufB, NPIX, 64, 32, dwb, DWD, 32, nullptr);
    k_gemm_tn<128, 128, 32, 1><<<dim3(1, NPIX / 128), 256>>>(
        bufB, pw1_w, pw1_b, bufA, NPIX, 128, 64, dwb, DWD, 96, nullptr);
    k_gemm_tn<128, 128, 32, 1><<<dim3(2, NPIX / 128), 256>>>(
        bufA, pw2_w, pw2_b, bufB, NPIX, 256, 128, dwb, DWD, 224, nullptr);
    k_gemm_tn<128, 128, 32, 1><<<dim3(4, NPIX / 128), 256>>>(
        bufB, pw3_w, pw3_b, bufA, NPIX, 512, 256, dwb, DWD, 480, nullptr);
    // 7. pout + residual: x1 = xt + g1 * (y @ pout^T + b)
    k_gemm_tn<128, 128, 32, 2><<<dim3(4, NPIX / 128), 256>>>(
        bufA, pout_w, pout_b, x1, NPIX, CDIM, CDIM, xt, CDIM, 0, g1);
    // 8. LN2
    k_ln_rows<<<NPIX / 8, 256>>>(x1, ln2_w, ln2_b, ln2o);
    // 9. fc1 + exact GELU
    k_gemm_tn<128, 128, 32, 3><<<dim3(HDIM / 128, NPIX / 128), 256>>>(
        ln2o, fc1_w, fc1_b, hbuf, NPIX, HDIM, CDIM, nullptr, 0, 0, nullptr);
    // 10. fc2
    k_gemm_tn<128, 128, 32, 0><<<dim3(CDIM / 128, NPIX / 128), 256>>>(
        hbuf, fc2_w, fc2_b, mbuf, NPIX, CDIM, HDIM, nullptr, 0, 0, nullptr);
    // 11. out = x1 + g2*m, back to NCHW
    k_final_out<<<tgrid, tpb32>>>(x1, mbuf, g2, out);
}

// round 5
// speedup vs baseline: 3.7570x; 3.7570x over previous
#include <cuda_runtime.h>
#include <cuda_bf16.h>
#include <cstdint>
#include <math.h>

// ---------------- problem constants ----------------
#define NPIX   16384     // B*H*W = 16*32*32
#define BATCH  16
#define CDIM   512
#define HWSZ   1024      // 32*32
#define FCH    1024      // pin output channels
#define DWD    992       // depthwise channels
#define HDIM   2048      // fc1 output

// ---------------- scratch (device globals; no allocation) ----------------
__device__ float          g_xt  [NPIX * CDIM];   // x in NHWC (fp32, residual)
__device__ float          g_x1  [NPIX * CDIM];   // x + g1*gnconv (fp32)
__device__ float          g_m   [NPIX * CDIM];   // fc2 output (fp32)
__device__ __nv_bfloat16  g_xln [NPIX * CDIM];
__device__ __nv_bfloat16  g_fused[NPIX * FCH];
__device__ __nv_bfloat16  g_dw  [NPIX * DWD];
__device__ __nv_bfloat16  g_bufA[NPIX * CDIM];
__device__ __nv_bfloat16  g_bufB[NPIX * CDIM];
__device__ __nv_bfloat16  g_ln2o[NPIX * CDIM];
__device__ __nv_bfloat16  g_h   [NPIX * HDIM];
// bf16 weights
__device__ __nv_bfloat16  g_wpin [FCH * CDIM];
__device__ __nv_bfloat16  g_w0   [64 * 32];
__device__ __nv_bfloat16  g_w1   [128 * 64];
__device__ __nv_bfloat16  g_w2   [256 * 128];
__device__ __nv_bfloat16  g_w3   [512 * 256];
__device__ __nv_bfloat16  g_wpout[CDIM * CDIM];
__device__ __nv_bfloat16  g_wfc1 [HDIM * CDIM];
__device__ __nv_bfloat16  g_wfc2 [CDIM * HDIM];

// ---------------- helpers ----------------
__device__ __forceinline__ uint32_t smem_u32(const void* p) {
    uint32_t a;
    asm("{ .reg .u64 t; cvta.to.shared.u64 t, %1; cvt.u32.u64 %0, t; }" : "=r"(a) : "l"(p));
    return a;
}
__device__ __forceinline__ void cp16(uint32_t dst, const void* src, uint32_t srcsz) {
    asm volatile("cp.async.cg.shared.global [%0], [%1], 16, %2;"
                 :: "r"(dst), "l"(src), "r"(srcsz));
}
#define CP_COMMIT() asm volatile("cp.async.commit_group;" ::: "memory")
#define CP_WAIT(n)  asm volatile("cp.async.wait_group %0;" :: "n"(n) : "memory")

__device__ __forceinline__ void ldmx4(uint32_t* f, uint32_t addr) {
    asm volatile("ldmatrix.sync.aligned.m8n8.x4.shared.b16 {%0,%1,%2,%3}, [%4];"
                 : "=r"(f[0]), "=r"(f[1]), "=r"(f[2]), "=r"(f[3]) : "r"(addr));
}
__device__ __forceinline__ void mma16816(float* c, const uint32_t* a, uint32_t b0, uint32_t b1) {
    asm volatile("mma.sync.aligned.m16n8k16.row.col.f32.bf16.bf16.f32 "
                 "{%0,%1,%2,%3}, {%4,%5,%6,%7}, {%8,%9}, {%0,%1,%2,%3};"
                 : "+f"(c[0]), "+f"(c[1]), "+f"(c[2]), "+f"(c[3])
                 : "r"(a[0]), "r"(a[1]), "r"(a[2]), "r"(a[3]), "r"(b0), "r"(b1));
}

// ---------------- f32 -> bf16 weight conversion ----------------
__global__ void k_f2b(const float* __restrict__ in, __nv_bfloat16* __restrict__ out, int n)
{
    int i = blockIdx.x * 256 + threadIdx.x;
    if (i * 2 + 1 < n) {
        float2 v = *(const float2*)(in + i * 2);
        *(__nv_bfloat162*)(out + i * 2) = __floats2bfloat162_rn(v.x, v.y);
    }
}

// ---------------- NCHW -> NHWC transpose (fp32) ----------------
__global__ void k_transpose_in(const float* __restrict__ x, float* __restrict__ xt)
{
    __shared__ float t[32][33];
    int b = blockIdx.z, c0 = blockIdx.y * 32, hw0 = blockIdx.x * 32;
    int tx = threadIdx.x, ty = threadIdx.y;
#pragma unroll
    for (int i = 0; i < 4; i++)
        t[ty + 8 * i][tx] = x[((size_t)(b * CDIM + c0 + ty + 8 * i)) * HWSZ + hw0 + tx];
    __syncthreads();
#pragma unroll
    for (int i = 0; i < 4; i++)
        xt[(size_t)(b * HWSZ + hw0 + ty + 8 * i) * CDIM + c0 + tx] = t[tx][ty + 8 * i];
}

// ---------------- row LayerNorm (fp32 in -> bf16 out) ----------------
__global__ void k_ln_rows(const float* __restrict__ in, const float* __restrict__ w,
                          const float* __restrict__ b, __nv_bfloat16* __restrict__ out)
{
    int row = blockIdx.x * 8 + (threadIdx.x >> 5);
    int lane = threadIdx.x & 31;
    const float4* r4 = (const float4*)(in + (size_t)row * CDIM);
    float4 v[4];
    float s = 0.f, ss = 0.f;
#pragma unroll
    for (int i = 0; i < 4; i++) {
        v[i] = r4[lane + 32 * i];
        s  += v[i].x + v[i].y + v[i].z + v[i].w;
        ss += v[i].x * v[i].x + v[i].y * v[i].y + v[i].z * v[i].z + v[i].w * v[i].w;
    }
#pragma unroll
    for (int o = 16; o; o >>= 1) {
        s  += __shfl_xor_sync(0xffffffffu, s, o);
        ss += __shfl_xor_sync(0xffffffffu, ss, o);
    }
    float mu = s * (1.f / 512.f);
    float rs = rsqrtf(ss * (1.f / 512.f) - mu * mu + 1e-6f);
    const float4* w4 = (const float4*)w;
    const float4* b4 = (const float4*)b;
#pragma unroll
    for (int i = 0; i < 4; i++) {
        int idx = lane + 32 * i;
        float4 ww = w4[idx], bb = b4[idx], vv = v[i];
        union { uint2 u; __nv_bfloat162 h[2]; } pk;
        pk.h[0] = __floats2bfloat162_rn((vv.x - mu) * rs * ww.x + bb.x,
                                        (vv.y - mu) * rs * ww.y + bb.y);
        pk.h[1] = __floats2bfloat162_rn((vv.z - mu) * rs * ww.z + bb.z,
                                        (vv.w - mu) * rs * ww.w + bb.w);
        *(uint2*)(out + (size_t)row * CDIM + idx * 4) = pk.u;
    }
}

// ---------------- bf16 warp-MMA GEMM: out[M,N] = A[M,K] @ W[N,K]^T + epi ----------------
// 128x128 CTA tile, BK=32, 8 warps (4 m x 2 n), warp tile 32x64.
// EPI 0: +bias -> bf16
// EPI 1: (+bias) * gate[r*ldg + goff + n] -> bf16
// EPI 2: res[r*N + n] + gamma[n]*(+bias) -> fp32
// EPI 3: gelu(+bias) -> bf16
// EPI 4: +bias -> fp32
#define PAD_ROW 40          // bf16 elems per smem row (80 bytes)
template <int EPI>
__global__ void __launch_bounds__(256)
k_gemm_mma(const __nv_bfloat16* __restrict__ A, const __nv_bfloat16* __restrict__ W,
           const float* __restrict__ bias, void* __restrict__ out,
           int M, int N, int K,
           const __nv_bfloat16* __restrict__ gate, int ldg, int goff,
           const float* __restrict__ res, const float* __restrict__ gamma)
{
    __shared__ __align__(16) __nv_bfloat16 sA[2][128 * PAD_ROW];
    __shared__ __align__(16) __nv_bfloat16 sB[2][128 * PAD_ROW];

    int tid = threadIdx.x, wid = tid >> 5, lane = tid & 31;
    int wm = wid & 3, wn = wid >> 2;
    int m0 = blockIdx.y * 128, n0 = blockIdx.x * 128;
    int nt = min(128, N - n0);

    uint32_t sAu[2] = { smem_u32(&sA[0][0]), smem_u32(&sA[1][0]) };
    uint32_t sBu[2] = { smem_u32(&sB[0][0]), smem_u32(&sB[1][0]) };

    float acc[2][8][4];
#pragma unroll
    for (int i = 0; i < 2; i++)
#pragma unroll
        for (int j = 0; j < 8; j++)
#pragma unroll
            for (int q = 0; q < 4; q++) acc[i][j][q] = 0.f;

    int T = K >> 5;   // BK = 32

    // tile loaders: 128 rows x 4 chunks of 16B
    auto loadA = [&](int k0, int buf) {
#pragma unroll
        for (int id = tid; id < 512; id += 256) {
            int r = id >> 2, c = id & 3;
            cp16(sAu[buf] + r * 80 + c * 16, A + (size_t)(m0 + r) * K + k0 + c * 8, 16);
        }
    };
    auto loadB = [&](int k0, int buf) {
#pragma unroll
        for (int id = tid; id < 512; id += 256) {
            int r = id >> 2, c = id & 3;
            int gr = n0 + r;
            const __nv_bfloat16* src = W + (size_t)(gr < N ? gr : 0) * K + k0 + c * 8;
            cp16(sBu[buf] + r * 80 + c * 16, src, gr < N ? 16u : 0u);
        }
    };

    loadA(0, 0); loadB(0, 0); CP_COMMIT();

    for (int it = 0; it < T; it++) {
        int buf = it & 1;
        if (it + 1 < T) {
            loadA((it + 1) * 32, buf ^ 1);
            loadB((it + 1) * 32, buf ^ 1);
            CP_COMMIT();
            CP_WAIT(1);
        } else {
            CP_WAIT(0);
        }
        __syncthreads();

        uint32_t aBase = sAu[buf] + (wm * 32 + (lane & 15)) * 80 + ((lane >> 4) * 16);
        uint32_t bBase = sBu[buf] + (wn * 64 + (lane & 15)) * 80 + ((lane >> 4) * 16);
#pragma unroll
        for (int ks = 0; ks < 2; ks++) {
            uint32_t af[2][4], bf[4][4];
#pragma unroll
            for (int am = 0; am < 2; am++)
                ldmx4(af[am], aBase + am * 16 * 80 + ks * 32);
#pragma unroll
            for (int bp = 0; bp < 4; bp++)
                ldmx4(bf[bp], bBase + bp * 16 * 80 + ks * 32);
#pragma unroll
            for (int am = 0; am < 2; am++)
#pragma unroll
                for (int na = 0; na < 8; na++)
                    mma16816(acc[am][na], af[am], bf[na >> 1][na & 1], bf[na >> 1][(na & 1) + 2]);
        }
        __syncthreads();
    }

    // ---------------- epilogue ----------------
    int rbase = m0 + wm * 32 + (lane >> 2);
    int cbase = wn * 64 + (lane & 3) * 2;      // relative to n0
#pragma unroll
    for (int am = 0; am < 2; am++) {
#pragma unroll
        for (int na = 0; na < 8; na++) {
            int cr = cbase + na * 8;
            if (cr >= nt) continue;
            int col = n0 + cr;
            float2 bs = *(const float2*)(bias + col);
#pragma unroll
            for (int h = 0; h < 2; h++) {       // row halves (+0 / +8)
                int row = rbase + am * 16 + h * 8;
                float v0 = acc[am][na][h * 2 + 0] + bs.x;
                float v1 = acc[am][na][h * 2 + 1] + bs.y;
                if (EPI == 1) {
                    __nv_bfloat162 gt = *(const __nv_bfloat162*)
                        (gate + (size_t)row * ldg + goff + col);
                    v0 *= __bfloat162float(gt.x);
                    v1 *= __bfloat162float(gt.y);
                }
                if (EPI == 3) {
                    v0 = 0.5f * v0 * (1.f + erff(v0 * 0.70710678118654752f));
                    v1 = 0.5f * v1 * (1.f + erff(v1 * 0.70710678118654752f));
                }
                if (EPI == 2) {
                    const float2 rr = *(const float2*)(res + (size_t)row * N + col);
                    const float2 gg = *(const float2*)(gamma + col);
                    v0 = rr.x + gg.x * v0;
                    v1 = rr.y + gg.y * v1;
                }
                if (EPI == 2 || EPI == 4) {
                    *(float2*)((float*)out + (size_t)row * N + col) = make_float2(v0, v1);
                } else {
                    *(__nv_bfloat162*)((__nv_bfloat16*)out + (size_t)row * N + col) =
                        __floats2bfloat162_rn(v0, v1);
                }
            }
        }
    }
}

// ---------------- depthwise 7x7 conv (bf16 in/out, fp32 acc) ----------------
__global__ void k_dwconv(const __nv_bfloat16* __restrict__ fused, const float* __restrict__ wgt,
                         const float* __restrict__ bias, __nv_bfloat16* __restrict__ out)
{
    __shared__ float sw[32 * 49];
    int cg = blockIdx.x;
    int cl = threadIdx.x & 31;
    int c  = cg * 32 + cl;
    for (int i = threadIdx.x; i < 32 * 49; i += 256)
        sw[i] = wgt[cg * 32 * 49 + i];
    __syncthreads();

    int p = blockIdx.y * 8 + (threadIdx.x >> 5);
    int b = p >> 10, hw = p & 1023, h = hw >> 5, w = hw & 31;
    const __nv_bfloat16* base = fused + (size_t)(b * HWSZ) * FCH + 32 + c;
    float acc = bias[c];
#pragma unroll
    for (int kh = 0; kh < 7; kh++) {
        int hh = h + kh - 3;
        if ((unsigned)hh < 32u) {
#pragma unroll
            for (int kw = 0; kw < 7; kw++) {
                int ww = w + kw - 3;
                if ((unsigned)ww < 32u)
                    acc += __bfloat162float(base[(size_t)(hh * 32 + ww) * FCH])
                         * sw[cl * 49 + kh * 7 + kw];
            }
        }
    }
    out[(size_t)p * DWD + c] = __float2bfloat16(acc);
}

// ---------------- y0 = pwa * dw0 (2 elems/thread) ----------------
__global__ void k_mul_pwa(const __nv_bfloat16* __restrict__ fused,
                          const __nv_bfloat16* __restrict__ dw,
                          __nv_bfloat16* __restrict__ out)
{
    int idx = blockIdx.x * 256 + threadIdx.x;   // over NPIX*16
    int p = idx >> 4, c = (idx & 15) * 2;
    __nv_bfloat162 a = *(const __nv_bfloat162*)(fused + (size_t)p * FCH + c);
    __nv_bfloat162 d = *(const __nv_bfloat162*)(dw + (size_t)p * DWD + c);
    *(__nv_bfloat162*)(out + (size_t)p * 32 + c) =
        __floats2bfloat162_rn(__bfloat162float(a.x) * __bfloat162float(d.x),
                              __bfloat162float(a.y) * __bfloat162float(d.y));
}

// ---------------- final: out(NCHW) = x1 + g2*m ----------------
__global__ void k_final_out(const float* __restrict__ x1, const float* __restrict__ m,
                            const float* __restrict__ g2, float* __restrict__ out)
{
    __shared__ float t[32][33];
    int b = blockIdx.z, c0 = blockIdx.y * 32, hw0 = blockIdx.x * 32;
    int tx = threadIdx.x, ty = threadIdx.y;
#pragma unroll
    for (int i = 0; i < 4; i++) {
        int p = b * HWSZ + hw0 + ty + 8 * i;
        int c = c0 + tx;
        size_t o = (size_t)p * CDIM + c;
        t[ty + 8 * i][tx] = x1[o] + g2[c] * m[o];
    }
    __syncthreads();
#pragma unroll
    for (int i = 0; i < 4; i++)
        out[((size_t)(b * CDIM + c0 + ty + 8 * i)) * HWSZ + hw0 + tx] = t[tx][ty + 8 * i];
}

// ---------------- host orchestration ----------------
static float* symf(const void* s) { void* p = nullptr; cudaGetSymbolAddress(&p, s); return (float*)p; }
static __nv_bfloat16* symb(const void* s) { void* p = nullptr; cudaGetSymbolAddress(&p, s); return (__nv_bfloat16*)p; }

extern "C" void kernel_launch(void* const* d_in, const int* in_sizes, int n_in,
                              void* d_out, int out_size)
{
    const float* x      = (const float*)d_in[0];
    const float* ln1_w  = (const float*)d_in[1];
    const float* ln1_b  = (const float*)d_in[2];
    const float* pin_w  = (const float*)d_in[3];
    const float* pin_b  = (const float*)d_in[4];
    const float* dw_w   = (const float*)d_in[5];
    const float* dw_b   = (const float*)d_in[6];
    const float* pw0_w  = (const float*)d_in[7];
    const float* pw0_b  = (const float*)d_in[8];
    const float* pw1_w  = (const float*)d_in[9];
    const float* pw1_b  = (const float*)d_in[10];
    const float* pw2_w  = (const float*)d_in[11];
    const float* pw2_b  = (const float*)d_in[12];
    const float* pw3_w  = (const float*)d_in[13];
    const float* pw3_b  = (const float*)d_in[14];
    const float* pout_w = (const float*)d_in[15];
    const float* pout_b = (const float*)d_in[16];
    const float* ln2_w  = (const float*)d_in[17];
    const float* ln2_b  = (const float*)d_in[18];
    const float* fc1_w  = (const float*)d_in[19];
    const float* fc1_b  = (const float*)d_in[20];
    const float* fc2_w  = (const float*)d_in[21];
    const float* fc2_b  = (const float*)d_in[22];
    const float* g1     = (const float*)d_in[23];
    const float* g2     = (const float*)d_in[24];
    float* out = (float*)d_out;

    float* xt   = symf(g_xt);
    float* x1   = symf(g_x1);
    float* mbuf = symf(g_m);
    __nv_bfloat16* xln   = symb(g_xln);
    __nv_bfloat16* fused = symb(g_fused);
    __nv_bfloat16* dwb   = symb(g_dw);
    __nv_bfloat16* bufA  = symb(g_bufA);
    __nv_bfloat16* bufB  = symb(g_bufB);
    __nv_bfloat16* ln2o  = symb(g_ln2o);
    __nv_bfloat16* hbuf  = symb(g_h);
    __nv_bfloat16* wpin  = symb(g_wpin);
    __nv_bfloat16* w0    = symb(g_w0);
    __nv_bfloat16* w1    = symb(g_w1);
    __nv_bfloat16* w2    = symb(g_w2);
    __nv_bfloat16* w3    = symb(g_w3);
    __nv_bfloat16* wpout = symb(g_wpout);
    __nv_bfloat16* wfc1  = symb(g_wfc1);
    __nv_bfloat16* wfc2  = symb(g_wfc2);

    // weight conversion
    auto cvt = [](const float* s, __nv_bfloat16* d, int n) {
        k_f2b<<<(n / 2 + 255) / 256, 256>>>(s, d, n);
    };
    cvt(pin_w,  wpin,  FCH * CDIM);
    cvt(pw0_w,  w0,    64 * 32);
    cvt(pw1_w,  w1,    128 * 64);
    cvt(pw2_w,  w2,    256 * 128);
    cvt(pw3_w,  w3,    512 * 256);
    cvt(pout_w, wpout, CDIM * CDIM);
    cvt(fc1_w,  wfc1,  HDIM * CDIM);
    cvt(fc2_w,  wfc2,  CDIM * HDIM);

    dim3 tpb32(32, 8);
    dim3 tgrid(32, 16, BATCH);

    // 1. NCHW -> NHWC
    k_transpose_in<<<tgrid, tpb32>>>(x, xt);
    // 2. LN1 (fp32 -> bf16)
    k_ln_rows<<<NPIX / 8, 256>>>(xt, ln1_w, ln1_b, xln);
    // 3. pin
    k_gemm_mma<0><<<dim3(FCH / 128, NPIX / 128), 256>>>(
        xln, wpin, pin_b, fused, NPIX, FCH, CDIM, nullptr, 0, 0, nullptr, nullptr);
    // 4. depthwise
    k_dwconv<<<dim3(31, NPIX / 8), 256>>>(fused, dw_w, dw_b, dwb);
    // 5. y0 = pwa * dw0
    k_mul_pwa<<<NPIX * 16 / 256, 256>>>(fused, dwb, bufA);
    // 6. gated pw chain
    k_gemm_mma<1><<<dim3(1, NPIX / 128), 256>>>(
        bufA, w0, pw0_b, bufB, NPIX, 64, 32, dwb, DWD, 32, nullptr, nullptr);
    k_gemm_mma<1><<<dim3(1, NPIX / 128), 256>>>(
        bufB, w1, pw1_b, bufA, NPIX, 128, 64, dwb, DWD, 96, nullptr, nullptr);
    k_gemm_mma<1><<<dim3(2, NPIX / 128), 256>>>(
        bufA, w2, pw2_b, bufB, NPIX, 256, 128, dwb, DWD, 224, nullptr, nullptr);
    k_gemm_mma<1><<<dim3(4, NPIX / 128), 256>>>(
        bufB, w3, pw3_b, bufA, NPIX, 512, 256, dwb, DWD, 480, nullptr, nullptr);
    // 7. pout + residual -> x1 (fp32)
    k_gemm_mma<2><<<dim3(4, NPIX / 128), 256>>>(
        bufA, wpout, pout_b, x1, NPIX, CDIM, CDIM, nullptr, 0, 0, xt, g1);
    // 8. LN2 (fp32 -> bf16)
    k_ln_rows<<<NPIX / 8, 256>>>(x1, ln2_w, ln2_b, ln2o);
    // 9. fc1 + GELU
    k_gemm_mma<3><<<dim3(HDIM / 128, NPIX / 128), 256>>>(
        ln2o, wfc1, fc1_b, hbuf, NPIX, HDIM, CDIM, nullptr, 0, 0, nullptr, nullptr);
    // 10. fc2 (fp32 out)
    k_gemm_mma<4><<<dim3(CDIM / 128, NPIX / 128), 256>>>(
        hbuf, wfc2, fc2_b, mbuf, NPIX, CDIM, HDIM, nullptr, 0, 0, nullptr, nullptr);
    // 11. out = x1 + g2*m -> NCHW
    k_final_out<<<tgrid, tpb32>>>(x1, mbuf, g2, out);
}